// round 16
// baseline (speedup 1.0000x reference)
#include <cuda_runtime.h>
#include <cuda_fp16.h>
#include <cstdint>
#include <math.h>

#define HID 2048
#define SLEN 2048
#define NBATCH 2
#define MROWS 4096
#define NHEADS 16
#define HD 128
#define FFD 8192

// ---------------- scratch (device globals; no allocations) ----------------
__device__ float g_mods[NBATCH * 6 * HID];
__device__ __half g_xmod16[(size_t)MROWS * HID];
__device__ __half g_q16[(size_t)MROWS * HID];
__device__ __half g_k16[(size_t)MROWS * HID];
__device__ __half g_v16[(size_t)MROWS * HID];
__device__ __half g_attn16[(size_t)MROWS * HID];
__device__ float g_h2[(size_t)MROWS * HID];
__device__ __half g_ffg16[(size_t)MROWS * FFD];
__device__ __half g_w16qkv[(size_t)3 * HID * HID];
__device__ __half g_w16o[(size_t)HID * HID];
__device__ __half g_w16ff[(size_t)2 * FFD * HID];   // rows interleaved a0,g0,a1,g1,...
__device__ __half g_w16fo[(size_t)HID * FFD];

// ---------------- helpers ----------------
__device__ __forceinline__ void mma16(float* c, const uint32_t* a, uint32_t b0, uint32_t b1) {
    asm volatile(
        "mma.sync.aligned.m16n8k16.row.col.f32.f16.f16.f32 "
        "{%0,%1,%2,%3}, {%4,%5,%6,%7}, {%8,%9}, {%0,%1,%2,%3};\n"
        : "+f"(c[0]), "+f"(c[1]), "+f"(c[2]), "+f"(c[3])
        : "r"(a[0]), "r"(a[1]), "r"(a[2]), "r"(a[3]), "r"(b0), "r"(b1));
}

__device__ __forceinline__ void ldsm4(uint32_t& r0, uint32_t& r1, uint32_t& r2,
                                      uint32_t& r3, uint32_t addr) {
    asm volatile("ldmatrix.sync.aligned.m8n8.x4.shared.b16 {%0,%1,%2,%3}, [%4];\n"
                 : "=r"(r0), "=r"(r1), "=r"(r2), "=r"(r3) : "r"(addr));
}

__device__ __forceinline__ void ldsm4t(uint32_t& r0, uint32_t& r1, uint32_t& r2,
                                       uint32_t& r3, uint32_t addr) {
    asm volatile("ldmatrix.sync.aligned.m8n8.x4.trans.shared.b16 {%0,%1,%2,%3}, [%4];\n"
                 : "=r"(r0), "=r"(r1), "=r"(r2), "=r"(r3) : "r"(addr));
}

__device__ __forceinline__ void cp16(uint32_t dst, const void* src) {
    asm volatile("cp.async.cg.shared.global [%0], [%1], 16;\n" :: "r"(dst), "l"(src));
}
#define CP_COMMIT() asm volatile("cp.async.commit_group;\n")
#define CP_WAIT1()  asm volatile("cp.async.wait_group 1;\n" ::: "memory")
#define CP_COMMIT_WAIT0() asm volatile("cp.async.commit_group;\ncp.async.wait_group 0;\n" ::: "memory")

__device__ __forceinline__ uint32_t smem_u32(const void* p) {
    return (uint32_t)__cvta_generic_to_shared(p);
}

__device__ __forceinline__ uint32_t pack2(float x, float y) {
    __half2 h = __floats2half2_rn(x, y);
    return *reinterpret_cast<uint32_t*>(&h);
}

// ---------------- fused prep kernel ----------------
// job A (blocks [0,96)):      g_mods = sst + temb
// job B (blocks [96,4192)):   xmod fp16 (mods recomputed inline from sst/temb)
// job C (blocks [4192,7264)): QKV weight conversion fp32->fp16
#define PREP_A 96
#define PREP_B 4096
#define PREP_C 3072
#define PREP_BLOCKS (PREP_A + PREP_B + PREP_C)
#define QKV_CH (3LL * HID * HID / 4)

__global__ void k_prep(const float* __restrict__ hidden,
                       const float* __restrict__ temb, const float* __restrict__ sst,
                       const float* __restrict__ Wq, const float* __restrict__ Wk,
                       const float* __restrict__ Wv) {
    int blk = blockIdx.x;
    int tidl = threadIdx.x;
    if (blk < PREP_A) {
        int i = blk * 256 + tidl;
        if (i < NBATCH * 6 * HID) {
            int h = i & (HID - 1);
            int r = i >> 11;
            int b = r / 6, mi = r % 6;
            g_mods[i] = sst[mi * HID + h] + temb[b * HID + h];
        }
        return;
    }
    if (blk < PREP_A + PREP_B) {
        int t = (blk - PREP_A) * 256 + tidl;
        #pragma unroll
        for (int it = 0; it < 2; it++) {
            int i4 = t + it * (MROWS * HID / 8);
            int i = i4 * 4;
            int h = i & (HID - 1);
            int b = i >> 22;
            float4 hv = *reinterpret_cast<const float4*>(hidden + i);
            const float* tb = temb + b * HID;
            float x0 = hv.x * (1.f + sst[HID + h + 0] + tb[h + 0]) + sst[h + 0] + tb[h + 0];
            float x1 = hv.y * (1.f + sst[HID + h + 1] + tb[h + 1]) + sst[h + 1] + tb[h + 1];
            float x2 = hv.z * (1.f + sst[HID + h + 2] + tb[h + 2]) + sst[h + 2] + tb[h + 2];
            float x3 = hv.w * (1.f + sst[HID + h + 3] + tb[h + 3]) + sst[h + 3] + tb[h + 3];
            __half2* o = reinterpret_cast<__half2*>(g_xmod16 + i);
            o[0] = __floats2half2_rn(x0, x1);
            o[1] = __floats2half2_rn(x2, x3);
        }
        return;
    }
    // job C: QKV weights, 4 chunks/thread
    int64_t b0 = (int64_t)(blk - PREP_A - PREP_B) * 1024 + tidl;
    const float4* src[4];
    __half2* dst[4];
    #pragma unroll
    for (int it = 0; it < 4; it++) {
        int64_t i = b0 + it * 256;
        int64_t per = QKV_CH / 3;
        int seg = (int)(i / per);
        int64_t j = i - (int64_t)seg * per;
        const float* W = (seg == 0) ? Wq : (seg == 1) ? Wk : Wv;
        src[it] = reinterpret_cast<const float4*>(W) + j;
        dst[it] = reinterpret_cast<__half2*>(g_w16qkv + i * 4);
    }
    float4 v[4];
    #pragma unroll
    for (int it = 0; it < 4; it++) v[it] = *src[it];
    #pragma unroll
    for (int it = 0; it < 4; it++) {
        dst[it][0] = __floats2half2_rn(v[it].x, v[it].y);
        dst[it][1] = __floats2half2_rn(v[it].z, v[it].w);
    }
}

// rest-weight conversion constants (Wo | Wff-interleaved | Wfo)
#define WO_CH  ((int64_t)HID * HID / 4)
#define FF_CH  (2LL * FFD * HID / 4)
#define FO_CH  ((int64_t)HID * FFD / 4)
#define REST_CH (WO_CH + FF_CH + FO_CH)     // 13,631,488 = 65536 * 208
#define NEXTRA_Y 8                          // 256 extra blocks on the QKV GEMM grid

__device__ __forceinline__ void conv_rest_chunk(
    int64_t j, const float* __restrict__ Wo,
    const float* __restrict__ Wff, const float* __restrict__ Wfo) {
    const float4* s;
    __half2* d;
    if (j < WO_CH) {
        s = reinterpret_cast<const float4*>(Wo) + j;
        d = reinterpret_cast<__half2*>(g_w16o + j * 4);
    } else if (j < WO_CH + FF_CH) {
        int64_t jj = j - WO_CH;
        int r = (int)(jj >> 9);
        int c4 = (int)(jj & 511) << 2;
        int sr = (r & 1) ? (FFD + (r >> 1)) : (r >> 1);
        s = reinterpret_cast<const float4*>(Wff + (size_t)sr * HID + c4);
        d = reinterpret_cast<__half2*>(g_w16ff + (size_t)r * HID + c4);
    } else {
        int64_t jj = j - WO_CH - FF_CH;
        s = reinterpret_cast<const float4*>(Wfo) + jj;
        d = reinterpret_cast<__half2*>(g_w16fo + jj * 4);
    }
    float4 v = *s;
    d[0] = __floats2half2_rn(v.x, v.y);
    d[1] = __floats2half2_rn(v.z, v.w);
}

// Per-head LayerNorm on fp16 vectors; q (scaled) and k in one launch.
#define NVEC (MROWS * NHEADS)
__global__ void k_ln16qk(__half* __restrict__ Qv, __half* __restrict__ Kv, float qmul) {
    int vec = blockIdx.x * 8 + (threadIdx.x >> 5);
    int lane = threadIdx.x & 31;
    __half* X;
    float mul;
    if (vec < NVEC) { X = Qv; mul = qmul; }
    else            { X = Kv; mul = 1.0f; vec -= NVEC; }
    uint2* p = reinterpret_cast<uint2*>(X) + (size_t)vec * 32 + lane;
    uint2 u = *p;
    __half2 h0 = *reinterpret_cast<__half2*>(&u.x);
    __half2 h1 = *reinterpret_cast<__half2*>(&u.y);
    float a = __half2float(h0.x), b = __half2float(h0.y);
    float c = __half2float(h1.x), d = __half2float(h1.y);
    float s = a + b + c + d;
    #pragma unroll
    for (int o = 16; o; o >>= 1) s += __shfl_xor_sync(0xffffffffu, s, o);
    float mean = s * (1.f / 128.f);
    float dx = a - mean, dy = b - mean, dz = c - mean, dw = d - mean;
    float q = dx * dx + dy * dy + dz * dz + dw * dw;
    #pragma unroll
    for (int o = 16; o; o >>= 1) q += __shfl_xor_sync(0xffffffffu, q, o);
    float r = rsqrtf(q * (1.f / 128.f) + 1e-5f) * mul;
    __half2 o0 = __floats2half2_rn(dx * r, dy * r);
    __half2 o1 = __floats2half2_rn(dz * r, dw * r);
    u.x = *reinterpret_cast<uint32_t*>(&o0);
    u.y = *reinterpret_cast<uint32_t*>(&o1);
    *p = u;
}

// ---------------- pipelined fp16 GEMM (R13-proven shape) ----------------
// Tile 128x128, BK=64, 3-stage cp.async, 256 threads (2x4 warps, 64x32 warp tiles),
// 2 CTAs/SM, one __syncthreads per k-tile.
// MODE 0: O-proj   MODE 1: QKV routing (fp16 out) + tail weight-conversion blocks
// MODE 2: FF1+GEGLU   MODE 3: FF2+final
#define ROWB 144
#define SA_B (128 * ROWB)
#define SSTG2 (2 * SA_B)            // 36864 B per stage
#define GEMM_SMEM_BYTES (3 * SSTG2) // 110592 B

template <int MODE>
__global__ __launch_bounds__(256, 2) void gemm_h(
    const __half* __restrict__ A, const __half* __restrict__ W,
    const float* __restrict__ bias0, const float* __restrict__ bias1,
    const float* __restrict__ bias2,
    float* __restrict__ C, int K, const float* __restrict__ resid,
    const float* __restrict__ cWo, const float* __restrict__ cWff,
    const float* __restrict__ cWfo)
{
    extern __shared__ char smc[];
    const int tid = threadIdx.x;
    constexpr bool MFAST = (MODE == 1 || MODE == 2);

    if (MODE == 1 && blockIdx.y >= 3 * HID / 128) {
        // ---- tail blocks: convert Wo/Wff/Wfo while QKV GEMM drains ----
        int lbid = (blockIdx.y - 3 * HID / 128) * gridDim.x + blockIdx.x;  // 0..255
        int64_t t0 = (int64_t)lbid * 256 + tid;                             // 0..65535
        for (int64_t j = t0; j < REST_CH; j += 4LL * 65536) {
            conv_rest_chunk(j,                cWo, cWff, cWfo);
            conv_rest_chunk(j + 65536,        cWo, cWff, cWfo);
            conv_rest_chunk(j + 2LL * 65536,  cWo, cWff, cWfo);
            conv_rest_chunk(j + 3LL * 65536,  cWo, cWff, cWfo);
        }
        return;
    }

    const int bm = MFAST ? blockIdx.x : blockIdx.y;
    const int bn = MFAST ? blockIdx.y : blockIdx.x;
    const int warp = tid >> 5, lane = tid & 31;
    const int wm = warp >> 2, wn = warp & 3;   // 2x4 warp grid, warp tile 64x32
    const int lg = lane >> 2, lt = lane & 3;
    const uint32_t smem_u = smem_u32(smc);

    const __half* aptr[4]; uint32_t dA[4];
    const __half* wptr[4]; uint32_t dB[4];
    #pragma unroll
    for (int i = 0; i < 4; i++) {
        int idx = tid + i * 256;           // 0..1023
        int r = idx >> 3, c8 = (idx & 7) << 3;
        aptr[i] = A + (size_t)(bm * 128 + r) * K + c8;
        dA[i] = (uint32_t)(r * ROWB + (idx & 7) * 16);
        wptr[i] = W + (size_t)(bn * 128 + r) * K + c8;
        dB[i] = (uint32_t)(SA_B + r * ROWB + (idx & 7) * 16);
    }

    float acc[4][4][4];
    #pragma unroll
    for (int i = 0; i < 4; i++)
        #pragma unroll
        for (int j = 0; j < 4; j++)
            #pragma unroll
            for (int r = 0; r < 4; r++) acc[i][j][r] = 0.f;

    const int nk = K >> 6;

    auto load_stage = [&](int kt, int st) {
        uint32_t base = smem_u + st * SSTG2;
        #pragma unroll
        for (int i = 0; i < 4; i++) cp16(base + dA[i], aptr[i] + kt * 64);
        #pragma unroll
        for (int i = 0; i < 4; i++) cp16(base + dB[i], wptr[i] + kt * 64);
        CP_COMMIT();
    };

    load_stage(0, 0);
    load_stage(1, 1);

    const uint32_t aoff = (uint32_t)((wm * 64 + (lane & 15)) * ROWB + ((lane & 16) ? 16 : 0));
    const uint32_t boff = (uint32_t)(SA_B + (wn * 32 + (lane & 7) + ((lane & 16) ? 8 : 0)) * ROWB +
                                     ((lane & 8) ? 16 : 0));

    int st = 0;
    for (int kt = 0; kt < nk; kt++) {
        CP_WAIT1();
        __syncthreads();
        if (kt + 2 < nk) {
            int nb = st + 2; if (nb >= 3) nb -= 3;
            load_stage(kt + 2, nb);
        } else {
            CP_COMMIT();
        }
        const uint32_t stb = smem_u + st * SSTG2;
        const uint32_t abase = stb + aoff;
        const uint32_t bbase = stb + boff;
        #pragma unroll
        for (int ks = 0; ks < 4; ks++) {            // 4 k-steps of 16
            uint32_t a[4][4];
            #pragma unroll
            for (int mf = 0; mf < 4; mf++)
                ldsm4(a[mf][0], a[mf][1], a[mf][2], a[mf][3],
                      abase + (uint32_t)(mf * 16 * ROWB + ks * 32));
            uint32_t b[4][2];
            #pragma unroll
            for (int nb2 = 0; nb2 < 2; nb2++) {
                uint32_t t0, t1, t2, t3;
                ldsm4(t0, t1, t2, t3, bbase + (uint32_t)(nb2 * 16 * ROWB + ks * 32));
                b[2 * nb2][0]     = t0;  b[2 * nb2][1]     = t1;
                b[2 * nb2 + 1][0] = t2;  b[2 * nb2 + 1][1] = t3;
            }
            #pragma unroll
            for (int mf = 0; mf < 4; mf++)
                #pragma unroll
                for (int nf = 0; nf < 4; nf++)
                    mma16(acc[mf][nf], a[mf], b[nf][0], b[nf][1]);
        }
        st = (st == 2) ? 0 : st + 1;
    }

    // ---------------- epilogue ----------------
    #pragma unroll
    for (int mf = 0; mf < 4; mf++) {
        #pragma unroll
        for (int nf = 0; nf < 4; nf++) {
            int row0 = bm * 128 + wm * 64 + mf * 16 + lg;
            int col0 = bn * 128 + wn * 32 + nf * 8 + lt * 2;
            float b0, b1;
            if (MODE == 1) {
                int seg = col0 >> 11;
                const float* bs = (seg == 0) ? bias0 : (seg == 1) ? bias1 : bias2;
                int colr = col0 & (HID - 1);
                b0 = bs[colr]; b1 = bs[colr + 1];
            } else if (MODE == 2) {
                int f = col0 >> 1;
                b0 = bias0[f]; b1 = bias0[FFD + f];
            } else {
                b0 = bias0[col0]; b1 = bias0[col0 + 1];
            }
            #pragma unroll
            for (int rr = 0; rr < 2; rr++) {
                int row = row0 + rr * 8;
                float v0 = acc[mf][nf][rr * 2 + 0] + b0;
                float v1 = acc[mf][nf][rr * 2 + 1] + b1;
                if (MODE == 1) {
                    int seg = col0 >> 11;
                    int colr = col0 & (HID - 1);
                    __half* dst = (seg == 0) ? g_q16 : (seg == 1) ? g_k16 : g_v16;
                    size_t o = (size_t)row * HID + colr;
                    *reinterpret_cast<__half2*>(&dst[o]) = __floats2half2_rn(v0, v1);
                } else if (MODE == 0) {
                    int b = row >> 11;
                    const float* md = g_mods + b * 6 * HID;
                    size_t o = (size_t)row * HID + col0;
                    float h0 = resid[o]     + md[2 * HID + col0]     * v0;
                    float h1 = resid[o + 1] + md[2 * HID + col0 + 1] * v1;
                    g_h2[o] = h0; g_h2[o + 1] = h1;
                    float x0 = h0 * (1.f + md[4 * HID + col0])     + md[3 * HID + col0];
                    float x1 = h1 * (1.f + md[4 * HID + col0 + 1]) + md[3 * HID + col0 + 1];
                    *reinterpret_cast<__half2*>(&g_xmod16[o]) = __floats2half2_rn(x0, x1);
                } else if (MODE == 2) {
                    float g = v1;
                    float gl = 0.5f * g * (1.f + tanhf(0.7978845608028654f * (g + 0.044715f * g * g * g)));
                    int f = col0 >> 1;
                    g_ffg16[(size_t)row * FFD + f] = __float2half_rn(v0 * gl);
                } else { // MODE == 3
                    int b = row >> 11;
                    size_t o = (size_t)row * HID + col0;
                    C[o]     = resid[o]     + g_mods[b * 6 * HID + 5 * HID + col0]     * v0;
                    C[o + 1] = resid[o + 1] + g_mods[b * 6 * HID + 5 * HID + col0 + 1] * v1;
                }
            }
        }
    }
}

// ---------------- fp16 flash attention (q128, single-buffered K/V) ----------------
#define ASTB 272
#define ATT_SMEM_BYTES ((128 + 64 + 64) * ASTB)   // 69632 B

__global__ __launch_bounds__(256, 2) void attn_h(
    const __half* __restrict__ Q, const __half* __restrict__ Kg,
    const __half* __restrict__ V, __half* __restrict__ Og)
{
    extern __shared__ __half hsm[];
    const uint32_t sQ = smem_u32(hsm);
    const uint32_t sK = sQ + 128 * ASTB;
    const uint32_t sV = sK + 64 * ASTB;

    const int tid = threadIdx.x, warp = tid >> 5, lane = tid & 31;
    const int lg = lane >> 2, lt = lane & 3;
    const int qt = blockIdx.x, bh = blockIdx.y;
    const int b = bh >> 4, h = bh & 15;
    const int m_base = warp * 16;

    const size_t base = (size_t)b * SLEN * HID + (size_t)h * HD;
    const __half* Qp = Q + base + (size_t)qt * 128 * HID;
    const __half* Kp = Kg + base;
    const __half* Vp = V + base;

    #pragma unroll
    for (int i = 0; i < 8; i++) {
        int idx = tid + i * 256;
        int r = idx >> 4, c = idx & 15;
        cp16(sQ + (uint32_t)(r * ASTB + c * 16), Qp + (size_t)r * HID + c * 8);
    }
    CP_COMMIT();

    float o[16][4];
    #pragma unroll
    for (int i = 0; i < 16; i++)
        #pragma unroll
        for (int j = 0; j < 4; j++) o[i][j] = 0.f;
    float m0 = -INFINITY, m1 = -INFINITY, l0 = 0.f, l1 = 0.f;

    const uint32_t aoff = sQ + (uint32_t)((m_base + (lane & 15)) * ASTB + ((lane & 16) ? 16 : 0));
    const uint32_t koff = sK + (uint32_t)(((lane & 7) + ((lane & 16) ? 8 : 0)) * ASTB +
                                          ((lane & 8) ? 16 : 0));
    const uint32_t voff = sV + (uint32_t)((lane & 15) * ASTB + ((lane & 16) ? 16 : 0));

    for (int kt = 0; kt < SLEN / 64; kt++) {
        __syncthreads();
        #pragma unroll
        for (int i = 0; i < 4; i++) {
            int idx = tid + i * 256;
            int r = idx >> 4, c = idx & 15;
            const size_t go = (size_t)(kt * 64 + r) * HID + c * 8;
            cp16(sK + (uint32_t)(r * ASTB + c * 16), Kp + go);
            cp16(sV + (uint32_t)(r * ASTB + c * 16), Vp + go);
        }
        CP_COMMIT_WAIT0();
        __syncthreads();

        float s_acc[8][4];
        #pragma unroll
        for (int nf = 0; nf < 8; nf++)
            #pragma unroll
            for (int j = 0; j < 4; j++) s_acc[nf][j] = 0.f;

        #pragma unroll
        for (int ks = 0; ks < 8; ks++) {
            uint32_t a[4];
            ldsm4(a[0], a[1], a[2], a[3], aoff + (uint32_t)(ks * 32));
            #pragma unroll
            for (int n2 = 0; n2 < 4; n2++) {
                uint32_t t0, t1, t2, t3;
                ldsm4(t0, t1, t2, t3, koff + (uint32_t)(n2 * 16 * ASTB + ks * 32));
                mma16(s_acc[2 * n2],     a, t0, t1);
                mma16(s_acc[2 * n2 + 1], a, t2, t3);
            }
        }

        float t0v = -INFINITY, t1v = -INFINITY;
        #pragma unroll
        for (int nf = 0; nf < 8; nf++) {
            t0v = fmaxf(t0v, fmaxf(s_acc[nf][0], s_acc[nf][1]));
            t1v = fmaxf(t1v, fmaxf(s_acc[nf][2], s_acc[nf][3]));
        }
        t0v = fmaxf(t0v, __shfl_xor_sync(0xffffffffu, t0v, 1));
        t0v = fmaxf(t0v, __shfl_xor_sync(0xffffffffu, t0v, 2));
        t1v = fmaxf(t1v, __shfl_xor_sync(0xffffffffu, t1v, 1));
        t1v = fmaxf(t1v, __shfl_xor_sync(0xffffffffu, t1v, 2));
        float nm0 = fmaxf(m0, t0v), nm1 = fmaxf(m1, t1v);
        float al0 = __expf(m0 - nm0), al1 = __expf(m1 - nm1);
        float ps0 = 0.f, ps1 = 0.f;
        #pragma unroll
        for (int nf = 0; nf < 8; nf++) {
            s_acc[nf][0] = __expf(s_acc[nf][0] - nm0);
            s_acc[nf][1] = __expf(s_acc[nf][1] - nm0);
            s_acc[nf][2] = __expf(s_acc[nf][2] - nm1);
            s_acc[nf][3] = __expf(s_acc[nf][3] - nm1);
            ps0 += s_acc[nf][0] + s_acc[nf][1];
            ps1 += s_acc[nf][2] + s_acc[nf][3];
        }
        ps0 += __shfl_xor_sync(0xffffffffu, ps0, 1);
        ps0 += __shfl_xor_sync(0xffffffffu, ps0, 2);
        ps1 += __shfl_xor_sync(0xffffffffu, ps1, 1);
        ps1 += __shfl_xor_sync(0xffffffffu, ps1, 2);
        l0 = l0 * al0 + ps0;  l1 = l1 * al1 + ps1;
        m0 = nm0;  m1 = nm1;
        #pragma unroll
        for (int nf = 0; nf < 16; nf++) {
            o[nf][0] *= al0; o[nf][1] *= al0; o[nf][2] *= al1; o[nf][3] *= al1;
        }

        #pragma unroll
        for (int ks = 0; ks < 4; ks++) {
            uint32_t pa[4];
            pa[0] = pack2(s_acc[2 * ks][0],     s_acc[2 * ks][1]);
            pa[1] = pack2(s_acc[2 * ks][2],     s_acc[2 * ks][3]);
            pa[2] = pack2(s_acc[2 * ks + 1][0], s_acc[2 * ks + 1][1]);
            pa[3] = pack2(s_acc[2 * ks + 1][2], s_acc[2 * ks + 1][3]);
            #pragma unroll
            for (int n2 = 0; n2 < 8; n2++) {
                uint32_t t0, t1, t2, t3;
                ldsm4t(t0, t1, t2, t3, voff + (uint32_t)(ks * 16 * ASTB + n2 * 32));
                mma16(o[2 * n2],     pa, t0, t1);
                mma16(o[2 * n2 + 1], pa, t2, t3);
            }
        }
    }

    float il0 = 1.f / l0, il1 = 1.f / l1;
    int row0 = qt * 128 + m_base + lg;
    #pragma unroll
    for (int nf = 0; nf < 16; nf++) {
        size_t oi = (size_t)(b * SLEN + row0) * HID + h * HD + nf * 8 + lt * 2;
        *reinterpret_cast<__half2*>(&Og[oi]) =
            __floats2half2_rn(o[nf][0] * il0, o[nf][1] * il0);
        *reinterpret_cast<__half2*>(&Og[oi + (size_t)8 * HID]) =
            __floats2half2_rn(o[nf][2] * il1, o[nf][3] * il1);
    }
}

// ---------------- launch ----------------
extern "C" void kernel_launch(void* const* d_in, const int* in_sizes, int n_in,
                              void* d_out, int out_size) {
    const float* hidden = (const float*)d_in[0];
    const float* temb   = (const float*)d_in[1];
    const float* Wq = (const float*)d_in[2];  const float* bq = (const float*)d_in[3];
    const float* Wk = (const float*)d_in[4];  const float* bk = (const float*)d_in[5];
    const float* Wv = (const float*)d_in[6];  const float* bv = (const float*)d_in[7];
    const float* Wo = (const float*)d_in[8];  const float* bo = (const float*)d_in[9];
    const float* Wff = (const float*)d_in[10]; const float* bff = (const float*)d_in[11];
    const float* Wfo = (const float*)d_in[12]; const float* bfo = (const float*)d_in[13];
    const float* sst = (const float*)d_in[14];
    float* out = (float*)d_out;

    void *p_xmod, *p_q, *p_k, *p_v, *p_attn, *p_h2, *p_ffg;
    void *p_wqkv, *p_wo, *p_wff, *p_wfo;
    cudaGetSymbolAddress(&p_xmod, g_xmod16);
    cudaGetSymbolAddress(&p_q, g_q16);
    cudaGetSymbolAddress(&p_k, g_k16);
    cudaGetSymbolAddress(&p_v, g_v16);
    cudaGetSymbolAddress(&p_attn, g_attn16);
    cudaGetSymbolAddress(&p_h2, g_h2);
    cudaGetSymbolAddress(&p_ffg, g_ffg16);
    cudaGetSymbolAddress(&p_wqkv, g_w16qkv);
    cudaGetSymbolAddress(&p_wo, g_w16o);
    cudaGetSymbolAddress(&p_wff, g_w16ff);
    cudaGetSymbolAddress(&p_wfo, g_w16fo);
    __half* xmod = (__half*)p_xmod;
    __half* q = (__half*)p_q; __half* k = (__half*)p_k; __half* v = (__half*)p_v;
    __half* attn = (__half*)p_attn; float* h2 = (float*)p_h2; __half* ffg = (__half*)p_ffg;
    __half* wqkv = (__half*)p_wqkv; __half* wo = (__half*)p_wo;
    __half* wff = (__half*)p_wff; __half* wfo = (__half*)p_wfo;

    cudaFuncSetAttribute(attn_h, cudaFuncAttributeMaxDynamicSharedMemorySize, ATT_SMEM_BYTES);
    cudaFuncSetAttribute(gemm_h<0>, cudaFuncAttributeMaxDynamicSharedMemorySize, GEMM_SMEM_BYTES);
    cudaFuncSetAttribute(gemm_h<1>, cudaFuncAttributeMaxDynamicSharedMemorySize, GEMM_SMEM_BYTES);
    cudaFuncSetAttribute(gemm_h<2>, cudaFuncAttributeMaxDynamicSharedMemorySize, GEMM_SMEM_BYTES);
    cudaFuncSetAttribute(gemm_h<3>, cudaFuncAttributeMaxDynamicSharedMemorySize, GEMM_SMEM_BYTES);

    // fused prep: mods + xmod + QKV weight conversion
    k_prep<<<PREP_BLOCKS, 256>>>(hidden, temb, sst, Wq, Wk, Wv);

    // fused QKV GEMM: [4096, 6144] (bm-fastest raster) + tail weight-conversion blocks
    gemm_h<1><<<dim3(MROWS / 128, 3 * HID / 128 + NEXTRA_Y), 256, GEMM_SMEM_BYTES>>>(
        xmod, wqkv, bq, bk, bv, nullptr, HID, nullptr, Wo, Wff, Wfo);

    // fused per-head LN on q (scaled) and k
    k_ln16qk<<<(2 * NVEC) / 8, 256>>>(q, k, 0.08838834764831845f);

    attn_h<<<dim3(SLEN / 128, NBATCH * NHEADS), 256, ATT_SMEM_BYTES>>>(q, k, v, attn);

    // O-proj + residual + mlp-modulation (bn-fastest)
    gemm_h<0><<<dim3(HID / 128, MROWS / 128), 256, GEMM_SMEM_BYTES>>>(
        attn, wo, bo, nullptr, nullptr, nullptr, HID, hidden, nullptr, nullptr, nullptr);

    // FF1 + GEGLU (bm-fastest)
    gemm_h<2><<<dim3(MROWS / 128, 2 * FFD / 128), 256, GEMM_SMEM_BYTES>>>(
        xmod, wff, bff, nullptr, nullptr, nullptr, HID, nullptr, nullptr, nullptr, nullptr);

    // FF2 + final residual (bn-fastest)
    gemm_h<3><<<dim3(HID / 128, MROWS / 128), 256, GEMM_SMEM_BYTES>>>(
        ffg, wfo, bfo, nullptr, nullptr, out, FFD, h2, nullptr, nullptr, nullptr);
}

// round 17
// speedup vs baseline: 1.0333x; 1.0333x over previous
#include <cuda_runtime.h>
#include <cuda_fp16.h>
#include <cstdint>
#include <math.h>

#define HID 2048
#define SLEN 2048
#define NBATCH 2
#define MROWS 4096
#define NHEADS 16
#define HD 128
#define FFD 8192

// ---------------- scratch (device globals; no allocations) ----------------
__device__ float g_mods[NBATCH * 6 * HID];
__device__ __half g_xmod16[(size_t)MROWS * HID];
__device__ __half g_q16[(size_t)MROWS * HID];
__device__ __half g_k16[(size_t)MROWS * HID];
__device__ __half g_v16[(size_t)MROWS * HID];
__device__ __half g_attn16[(size_t)MROWS * HID];
__device__ float g_h2[(size_t)MROWS * HID];
__device__ __half g_ffg16[(size_t)MROWS * FFD];
__device__ __half g_w16qkv[(size_t)3 * HID * HID];
__device__ __half g_w16o[(size_t)HID * HID];
__device__ __half g_w16ff[(size_t)2 * FFD * HID];   // rows interleaved a0,g0,a1,g1,...
__device__ __half g_w16fo[(size_t)HID * FFD];

// ---------------- helpers ----------------
__device__ __forceinline__ void mma16(float* c, const uint32_t* a, uint32_t b0, uint32_t b1) {
    asm volatile(
        "mma.sync.aligned.m16n8k16.row.col.f32.f16.f16.f32 "
        "{%0,%1,%2,%3}, {%4,%5,%6,%7}, {%8,%9}, {%0,%1,%2,%3};\n"
        : "+f"(c[0]), "+f"(c[1]), "+f"(c[2]), "+f"(c[3])
        : "r"(a[0]), "r"(a[1]), "r"(a[2]), "r"(a[3]), "r"(b0), "r"(b1));
}

__device__ __forceinline__ void ldsm4(uint32_t& r0, uint32_t& r1, uint32_t& r2,
                                      uint32_t& r3, uint32_t addr) {
    asm volatile("ldmatrix.sync.aligned.m8n8.x4.shared.b16 {%0,%1,%2,%3}, [%4];\n"
                 : "=r"(r0), "=r"(r1), "=r"(r2), "=r"(r3) : "r"(addr));
}

__device__ __forceinline__ void ldsm4t(uint32_t& r0, uint32_t& r1, uint32_t& r2,
                                       uint32_t& r3, uint32_t addr) {
    asm volatile("ldmatrix.sync.aligned.m8n8.x4.trans.shared.b16 {%0,%1,%2,%3}, [%4];\n"
                 : "=r"(r0), "=r"(r1), "=r"(r2), "=r"(r3) : "r"(addr));
}

__device__ __forceinline__ void cp16(uint32_t dst, const void* src) {
    asm volatile("cp.async.cg.shared.global [%0], [%1], 16;\n" :: "r"(dst), "l"(src));
}
#define CP_COMMIT() asm volatile("cp.async.commit_group;\n")
#define CP_WAIT1()  asm volatile("cp.async.wait_group 1;\n" ::: "memory")
#define CP_COMMIT_WAIT0() asm volatile("cp.async.commit_group;\ncp.async.wait_group 0;\n" ::: "memory")

__device__ __forceinline__ uint32_t smem_u32(const void* p) {
    return (uint32_t)__cvta_generic_to_shared(p);
}

__device__ __forceinline__ uint32_t pack2(float x, float y) {
    __half2 h = __floats2half2_rn(x, y);
    return *reinterpret_cast<uint32_t*>(&h);
}

// ---------------- prep / elementwise ----------------
__global__ void k_mods(const float* __restrict__ temb, const float* __restrict__ sst) {
    int i = blockIdx.x * 256 + threadIdx.x;
    if (i >= NBATCH * 6 * HID) return;
    int h = i & (HID - 1);
    int r = i >> 11;
    int b = r / 6, mi = r % 6;
    g_mods[i] = sst[mi * HID + h] + temb[b * HID + h];
}

__global__ void k_xmod1(const float* __restrict__ hidden) {
    int t = blockIdx.x * 256 + threadIdx.x;
    #pragma unroll
    for (int it = 0; it < 2; it++) {
        int i4 = t + it * (MROWS * HID / 8);
        int i = i4 * 4;
        int h = i & (HID - 1);
        int b = i >> 22;
        const float* md = g_mods + b * 6 * HID;
        float4 hv = *reinterpret_cast<const float4*>(hidden + i);
        float x0 = hv.x * (1.f + md[1 * HID + h + 0]) + md[0 * HID + h + 0];
        float x1 = hv.y * (1.f + md[1 * HID + h + 1]) + md[0 * HID + h + 1];
        float x2 = hv.z * (1.f + md[1 * HID + h + 2]) + md[0 * HID + h + 2];
        float x3 = hv.w * (1.f + md[1 * HID + h + 3]) + md[0 * HID + h + 3];
        __half2* o = reinterpret_cast<__half2*>(g_xmod16 + i);
        o[0] = __floats2half2_rn(x0, x1);
        o[1] = __floats2half2_rn(x2, x3);
    }
}

#define QKV_CH (3LL * HID * HID / 4)
#define WO_CH  ((int64_t)HID * HID / 4)
#define FF_CH  (2LL * FFD * HID / 4)
#define FO_CH  ((int64_t)HID * FFD / 4)
#define TOT_CH (QKV_CH + WO_CH + FF_CH + FO_CH)

__global__ void k_wprep(const float* __restrict__ Wq, const float* __restrict__ Wk,
                        const float* __restrict__ Wv, const float* __restrict__ Wo,
                        const float* __restrict__ Wff, const float* __restrict__ Wfo) {
    int64_t b0 = (int64_t)blockIdx.x * 1024 + threadIdx.x;
    const float4* src[4];
    __half2* dst[4];
    #pragma unroll
    for (int it = 0; it < 4; it++) {
        int64_t i = b0 + it * 256;
        if (i < QKV_CH) {
            int64_t per = QKV_CH / 3;
            int seg = (int)(i / per);
            int64_t j = i - (int64_t)seg * per;
            const float* W = (seg == 0) ? Wq : (seg == 1) ? Wk : Wv;
            src[it] = reinterpret_cast<const float4*>(W) + j;
            dst[it] = reinterpret_cast<__half2*>(g_w16qkv + i * 4);
        } else if (i < QKV_CH + WO_CH) {
            int64_t j = i - QKV_CH;
            src[it] = reinterpret_cast<const float4*>(Wo) + j;
            dst[it] = reinterpret_cast<__half2*>(g_w16o + j * 4);
        } else if (i < QKV_CH + WO_CH + FF_CH) {
            int64_t j = i - QKV_CH - WO_CH;
            int r = (int)(j >> 9);
            int c4 = (int)(j & 511) << 2;
            int sr = (r & 1) ? (FFD + (r >> 1)) : (r >> 1);
            src[it] = reinterpret_cast<const float4*>(Wff + (size_t)sr * HID + c4);
            dst[it] = reinterpret_cast<__half2*>(g_w16ff + (size_t)r * HID + c4);
        } else {
            int64_t j = i - QKV_CH - WO_CH - FF_CH;
            src[it] = reinterpret_cast<const float4*>(Wfo) + j;
            dst[it] = reinterpret_cast<__half2*>(g_w16fo + j * 4);
        }
    }
    float4 v[4];
    #pragma unroll
    for (int it = 0; it < 4; it++) v[it] = *src[it];
    #pragma unroll
    for (int it = 0; it < 4; it++) {
        dst[it][0] = __floats2half2_rn(v[it].x, v[it].y);
        dst[it][1] = __floats2half2_rn(v[it].z, v[it].w);
    }
}

#define NVEC (MROWS * NHEADS)
__global__ void k_ln16qk(__half* __restrict__ Qv, __half* __restrict__ Kv, float qmul) {
    int vec = blockIdx.x * 8 + (threadIdx.x >> 5);
    int lane = threadIdx.x & 31;
    __half* X;
    float mul;
    if (vec < NVEC) { X = Qv; mul = qmul; }
    else            { X = Kv; mul = 1.0f; vec -= NVEC; }
    uint2* p = reinterpret_cast<uint2*>(X) + (size_t)vec * 32 + lane;
    uint2 u = *p;
    __half2 h0 = *reinterpret_cast<__half2*>(&u.x);
    __half2 h1 = *reinterpret_cast<__half2*>(&u.y);
    float a = __half2float(h0.x), b = __half2float(h0.y);
    float c = __half2float(h1.x), d = __half2float(h1.y);
    float s = a + b + c + d;
    #pragma unroll
    for (int o = 16; o; o >>= 1) s += __shfl_xor_sync(0xffffffffu, s, o);
    float mean = s * (1.f / 128.f);
    float dx = a - mean, dy = b - mean, dz = c - mean, dw = d - mean;
    float q = dx * dx + dy * dy + dz * dz + dw * dw;
    #pragma unroll
    for (int o = 16; o; o >>= 1) q += __shfl_xor_sync(0xffffffffu, q, o);
    float r = rsqrtf(q * (1.f / 128.f) + 1e-5f) * mul;
    __half2 o0 = __floats2half2_rn(dx * r, dy * r);
    __half2 o1 = __floats2half2_rn(dz * r, dw * r);
    u.x = *reinterpret_cast<uint32_t*>(&o0);
    u.y = *reinterpret_cast<uint32_t*>(&o1);
    *p = u;
}

// ---------------- pipelined fp16 GEMM (R13-proven shape) ----------------
// Tile 128x128, BK=64, 3-stage cp.async, 256 threads (2x4 warps, 64x32 warp tiles),
// 2 CTAs/SM, one __syncthreads per k-tile.
// MODE 0: O-proj   MODE 1: QKV routing (fp16 out)   MODE 2: FF1+GEGLU   MODE 3: FF2+final
#define ROWB 144
#define SA_B (128 * ROWB)
#define SSTG2 (2 * SA_B)            // 36864 B per stage
#define GEMM_SMEM_BYTES (3 * SSTG2) // 110592 B

template <int MODE>
__global__ __launch_bounds__(256, 2) void gemm_h(
    const __half* __restrict__ A, const __half* __restrict__ W,
    const float* __restrict__ bias0, const float* __restrict__ bias1,
    const float* __restrict__ bias2,
    float* __restrict__ C, int K, const float* __restrict__ resid)
{
    extern __shared__ char smc[];
    const int tid = threadIdx.x;
    constexpr bool MFAST = (MODE == 1 || MODE == 2);
    const int bm = MFAST ? blockIdx.x : blockIdx.y;
    const int bn = MFAST ? blockIdx.y : blockIdx.x;
    const int warp = tid >> 5, lane = tid & 31;
    const int wm = warp >> 2, wn = warp & 3;   // 2x4 warp grid, warp tile 64x32
    const int lg = lane >> 2, lt = lane & 3;
    const uint32_t smem_u = smem_u32(smc);

    const __half* aptr[4]; uint32_t dA[4];
    const __half* wptr[4]; uint32_t dB[4];
    #pragma unroll
    for (int i = 0; i < 4; i++) {
        int idx = tid + i * 256;           // 0..1023
        int r = idx >> 3, c8 = (idx & 7) << 3;
        aptr[i] = A + (size_t)(bm * 128 + r) * K + c8;
        dA[i] = (uint32_t)(r * ROWB + (idx & 7) * 16);
        wptr[i] = W + (size_t)(bn * 128 + r) * K + c8;
        dB[i] = (uint32_t)(SA_B + r * ROWB + (idx & 7) * 16);
    }

    float acc[4][4][4];
    #pragma unroll
    for (int i = 0; i < 4; i++)
        #pragma unroll
        for (int j = 0; j < 4; j++)
            #pragma unroll
            for (int r = 0; r < 4; r++) acc[i][j][r] = 0.f;

    const int nk = K >> 6;

    auto load_stage = [&](int kt, int st) {
        uint32_t base = smem_u + st * SSTG2;
        #pragma unroll
        for (int i = 0; i < 4; i++) cp16(base + dA[i], aptr[i] + kt * 64);
        #pragma unroll
        for (int i = 0; i < 4; i++) cp16(base + dB[i], wptr[i] + kt * 64);
        CP_COMMIT();
    };

    load_stage(0, 0);
    load_stage(1, 1);

    const uint32_t aoff = (uint32_t)((wm * 64 + (lane & 15)) * ROWB + ((lane & 16) ? 16 : 0));
    const uint32_t boff = (uint32_t)(SA_B + (wn * 32 + (lane & 7) + ((lane & 16) ? 8 : 0)) * ROWB +
                                     ((lane & 8) ? 16 : 0));

    int st = 0;
    for (int kt = 0; kt < nk; kt++) {
        CP_WAIT1();
        __syncthreads();
        if (kt + 2 < nk) {
            int nb = st + 2; if (nb >= 3) nb -= 3;
            load_stage(kt + 2, nb);
        } else {
            CP_COMMIT();
        }
        const uint32_t stb = smem_u + st * SSTG2;
        const uint32_t abase = stb + aoff;
        const uint32_t bbase = stb + boff;
        #pragma unroll
        for (int ks = 0; ks < 4; ks++) {            // 4 k-steps of 16
            uint32_t a[4][4];
            #pragma unroll
            for (int mf = 0; mf < 4; mf++)
                ldsm4(a[mf][0], a[mf][1], a[mf][2], a[mf][3],
                      abase + (uint32_t)(mf * 16 * ROWB + ks * 32));
            uint32_t b[4][2];
            #pragma unroll
            for (int nb2 = 0; nb2 < 2; nb2++) {
                uint32_t t0, t1, t2, t3;
                ldsm4(t0, t1, t2, t3, bbase + (uint32_t)(nb2 * 16 * ROWB + ks * 32));
                b[2 * nb2][0]     = t0;  b[2 * nb2][1]     = t1;
                b[2 * nb2 + 1][0] = t2;  b[2 * nb2 + 1][1] = t3;
            }
            #pragma unroll
            for (int mf = 0; mf < 4; mf++)
                #pragma unroll
                for (int nf = 0; nf < 4; nf++)
                    mma16(acc[mf][nf], a[mf], b[nf][0], b[nf][1]);
        }
        st = (st == 2) ? 0 : st + 1;
    }

    // ---------------- epilogue ----------------
    #pragma unroll
    for (int mf = 0; mf < 4; mf++) {
        #pragma unroll
        for (int nf = 0; nf < 4; nf++) {
            int row0 = bm * 128 + wm * 64 + mf * 16 + lg;
            int col0 = bn * 128 + wn * 32 + nf * 8 + lt * 2;
            float b0, b1;
            if (MODE == 1) {
                int seg = col0 >> 11;
                const float* bs = (seg == 0) ? bias0 : (seg == 1) ? bias1 : bias2;
                int colr = col0 & (HID - 1);
                b0 = bs[colr]; b1 = bs[colr + 1];
            } else if (MODE == 2) {
                int f = col0 >> 1;
                b0 = bias0[f]; b1 = bias0[FFD + f];
            } else {
                b0 = bias0[col0]; b1 = bias0[col0 + 1];
            }
            #pragma unroll
            for (int rr = 0; rr < 2; rr++) {
                int row = row0 + rr * 8;
                float v0 = acc[mf][nf][rr * 2 + 0] + b0;
                float v1 = acc[mf][nf][rr * 2 + 1] + b1;
                if (MODE == 1) {
                    int seg = col0 >> 11;
                    int colr = col0 & (HID - 1);
                    __half* dst = (seg == 0) ? g_q16 : (seg == 1) ? g_k16 : g_v16;
                    size_t o = (size_t)row * HID + colr;
                    *reinterpret_cast<__half2*>(&dst[o]) = __floats2half2_rn(v0, v1);
                } else if (MODE == 0) {
                    int b = row >> 11;
                    const float* md = g_mods + b * 6 * HID;
                    size_t o = (size_t)row * HID + col0;
                    float h0 = resid[o]     + md[2 * HID + col0]     * v0;
                    float h1 = resid[o + 1] + md[2 * HID + col0 + 1] * v1;
                    g_h2[o] = h0; g_h2[o + 1] = h1;
                    float x0 = h0 * (1.f + md[4 * HID + col0])     + md[3 * HID + col0];
                    float x1 = h1 * (1.f + md[4 * HID + col0 + 1]) + md[3 * HID + col0 + 1];
                    *reinterpret_cast<__half2*>(&g_xmod16[o]) = __floats2half2_rn(x0, x1);
                } else if (MODE == 2) {
                    float g = v1;
                    float gl = 0.5f * g * (1.f + tanhf(0.7978845608028654f * (g + 0.044715f * g * g * g)));
                    int f = col0 >> 1;
                    g_ffg16[(size_t)row * FFD + f] = __float2half_rn(v0 * gl);
                } else { // MODE == 3
                    int b = row >> 11;
                    size_t o = (size_t)row * HID + col0;
                    C[o]     = resid[o]     + g_mods[b * 6 * HID + 5 * HID + col0]     * v0;
                    C[o + 1] = resid[o + 1] + g_mods[b * 6 * HID + 5 * HID + col0 + 1] * v1;
                }
            }
        }
    }
}

// ---------------- fp16 flash attention (q128, DOUBLE-buffered K/V) ----------------
#define ASTB 272
#define KVB (64 * ASTB)
#define ATT_SMEM_BYTES ((128 + 4 * 64) * ASTB)   // Q + 2*(K+V) = 104448 B

__global__ __launch_bounds__(256, 2) void attn_h(
    const __half* __restrict__ Q, const __half* __restrict__ Kg,
    const __half* __restrict__ V, __half* __restrict__ Og)
{
    extern __shared__ __half hsm[];
    const uint32_t sQ = smem_u32(hsm);
    const uint32_t sKV = sQ + 128 * ASTB;     // [K0 V0][K1 V1]

    const int tid = threadIdx.x, warp = tid >> 5, lane = tid & 31;
    const int lg = lane >> 2, lt = lane & 3;
    const int qt = blockIdx.x, bh = blockIdx.y;
    const int b = bh >> 4, h = bh & 15;
    const int m_base = warp * 16;

    const size_t base = (size_t)b * SLEN * HID + (size_t)h * HD;
    const __half* Qp = Q + base + (size_t)qt * 128 * HID;
    const __half* Kp = Kg + base;
    const __half* Vp = V + base;

    // Q tile: 2048 chunks / 256 threads
    #pragma unroll
    for (int i = 0; i < 8; i++) {
        int idx = tid + i * 256;
        int r = idx >> 4, c = idx & 15;
        cp16(sQ + (uint32_t)(r * ASTB + c * 16), Qp + (size_t)r * HID + c * 8);
    }
    CP_COMMIT();

    auto load_kv = [&](int kt, int buf) {
        uint32_t sK = sKV + buf * 2 * KVB;
        uint32_t sV = sK + KVB;
        #pragma unroll
        for (int i = 0; i < 4; i++) {
            int idx = tid + i * 256;
            int r = idx >> 4, c = idx & 15;
            const size_t go = (size_t)(kt * 64 + r) * HID + c * 8;
            cp16(sK + (uint32_t)(r * ASTB + c * 16), Kp + go);
            cp16(sV + (uint32_t)(r * ASTB + c * 16), Vp + go);
        }
        CP_COMMIT();
    };

    load_kv(0, 0);

    float o[16][4];
    #pragma unroll
    for (int i = 0; i < 16; i++)
        #pragma unroll
        for (int j = 0; j < 4; j++) o[i][j] = 0.f;
    float m0 = -INFINITY, m1 = -INFINITY, l0 = 0.f, l1 = 0.f;

    const uint32_t aoff = sQ + (uint32_t)((m_base + (lane & 15)) * ASTB + ((lane & 16) ? 16 : 0));
    const uint32_t koff0 = (uint32_t)(((lane & 7) + ((lane & 16) ? 8 : 0)) * ASTB +
                                      ((lane & 8) ? 16 : 0));
    const uint32_t voff0 = (uint32_t)((lane & 15) * ASTB + ((lane & 16) ? 16 : 0));

    for (int kt = 0; kt < SLEN / 64; kt++) {
        __syncthreads();                       // prior reads of the buffer being refilled
        if (kt + 1 < SLEN / 64) load_kv(kt + 1, (kt + 1) & 1);
        else CP_COMMIT();
        CP_WAIT1();                            // current buffer's loads complete
        __syncthreads();

        const uint32_t sK = sKV + (kt & 1) * 2 * KVB;
        const uint32_t koff = sK + koff0;
        const uint32_t voff = sK + KVB + voff0;

        float s_acc[8][4];
        #pragma unroll
        for (int nf = 0; nf < 8; nf++)
            #pragma unroll
            for (int j = 0; j < 4; j++) s_acc[nf][j] = 0.f;

        #pragma unroll
        for (int ks = 0; ks < 8; ks++) {
            uint32_t a[4];
            ldsm4(a[0], a[1], a[2], a[3], aoff + (uint32_t)(ks * 32));
            #pragma unroll
            for (int n2 = 0; n2 < 4; n2++) {
                uint32_t t0, t1, t2, t3;
                ldsm4(t0, t1, t2, t3, koff + (uint32_t)(n2 * 16 * ASTB + ks * 32));
                mma16(s_acc[2 * n2],     a, t0, t1);
                mma16(s_acc[2 * n2 + 1], a, t2, t3);
            }
        }

        float t0v = -INFINITY, t1v = -INFINITY;
        #pragma unroll
        for (int nf = 0; nf < 8; nf++) {
            t0v = fmaxf(t0v, fmaxf(s_acc[nf][0], s_acc[nf][1]));
            t1v = fmaxf(t1v, fmaxf(s_acc[nf][2], s_acc[nf][3]));
        }
        t0v = fmaxf(t0v, __shfl_xor_sync(0xffffffffu, t0v, 1));
        t0v = fmaxf(t0v, __shfl_xor_sync(0xffffffffu, t0v, 2));
        t1v = fmaxf(t1v, __shfl_xor_sync(0xffffffffu, t1v, 1));
        t1v = fmaxf(t1v, __shfl_xor_sync(0xffffffffu, t1v, 2));
        float nm0 = fmaxf(m0, t0v), nm1 = fmaxf(m1, t1v);
        float al0 = __expf(m0 - nm0), al1 = __expf(m1 - nm1);
        float ps0 = 0.f, ps1 = 0.f;
        #pragma unroll
        for (int nf = 0; nf < 8; nf++) {
            s_acc[nf][0] = __expf(s_acc[nf][0] - nm0);
            s_acc[nf][1] = __expf(s_acc[nf][1] - nm0);
            s_acc[nf][2] = __expf(s_acc[nf][2] - nm1);
            s_acc[nf][3] = __expf(s_acc[nf][3] - nm1);
            ps0 += s_acc[nf][0] + s_acc[nf][1];
            ps1 += s_acc[nf][2] + s_acc[nf][3];
        }
        ps0 += __shfl_xor_sync(0xffffffffu, ps0, 1);
        ps0 += __shfl_xor_sync(0xffffffffu, ps0, 2);
        ps1 += __shfl_xor_sync(0xffffffffu, ps1, 1);
        ps1 += __shfl_xor_sync(0xffffffffu, ps1, 2);
        l0 = l0 * al0 + ps0;  l1 = l1 * al1 + ps1;
        m0 = nm0;  m1 = nm1;
        #pragma unroll
        for (int nf = 0; nf < 16; nf++) {
            o[nf][0] *= al0; o[nf][1] *= al0; o[nf][2] *= al1; o[nf][3] *= al1;
        }

        #pragma unroll
        for (int ks = 0; ks < 4; ks++) {
            uint32_t pa[4];
            pa[0] = pack2(s_acc[2 * ks][0],     s_acc[2 * ks][1]);
            pa[1] = pack2(s_acc[2 * ks][2],     s_acc[2 * ks][3]);
            pa[2] = pack2(s_acc[2 * ks + 1][0], s_acc[2 * ks + 1][1]);
            pa[3] = pack2(s_acc[2 * ks + 1][2], s_acc[2 * ks + 1][3]);
            #pragma unroll
            for (int n2 = 0; n2 < 8; n2++) {
                uint32_t t0, t1, t2, t3;
                ldsm4t(t0, t1, t2, t3, voff + (uint32_t)(ks * 16 * ASTB + n2 * 32));
                mma16(o[2 * n2],     pa, t0, t1);
                mma16(o[2 * n2 + 1], pa, t2, t3);
            }
        }
    }

    float il0 = 1.f / l0, il1 = 1.f / l1;
    int row0 = qt * 128 + m_base + lg;
    #pragma unroll
    for (int nf = 0; nf < 16; nf++) {
        size_t oi = (size_t)(b * SLEN + row0) * HID + h * HD + nf * 8 + lt * 2;
        *reinterpret_cast<__half2*>(&Og[oi]) =
            __floats2half2_rn(o[nf][0] * il0, o[nf][1] * il0);
        *reinterpret_cast<__half2*>(&Og[oi + (size_t)8 * HID]) =
            __floats2half2_rn(o[nf][2] * il1, o[nf][3] * il1);
    }
}

// ---------------- launch ----------------
extern "C" void kernel_launch(void* const* d_in, const int* in_sizes, int n_in,
                              void* d_out, int out_size) {
    const float* hidden = (const float*)d_in[0];
    const float* temb   = (const float*)d_in[1];
    const float* Wq = (const float*)d_in[2];  const float* bq = (const float*)d_in[3];
    const float* Wk = (const float*)d_in[4];  const float* bk = (const float*)d_in[5];
    const float* Wv = (const float*)d_in[6];  const float* bv = (const float*)d_in[7];
    const float* Wo = (const float*)d_in[8];  const float* bo = (const float*)d_in[9];
    const float* Wff = (const float*)d_in[10]; const float* bff = (const float*)d_in[11];
    const float* Wfo = (const float*)d_in[12]; const float* bfo = (const float*)d_in[13];
    const float* sst = (const float*)d_in[14];
    float* out = (float*)d_out;

    void *p_xmod, *p_q, *p_k, *p_v, *p_attn, *p_h2, *p_ffg;
    void *p_wqkv, *p_wo, *p_wff, *p_wfo;
    cudaGetSymbolAddress(&p_xmod, g_xmod16);
    cudaGetSymbolAddress(&p_q, g_q16);
    cudaGetSymbolAddress(&p_k, g_k16);
    cudaGetSymbolAddress(&p_v, g_v16);
    cudaGetSymbolAddress(&p_attn, g_attn16);
    cudaGetSymbolAddress(&p_h2, g_h2);
    cudaGetSymbolAddress(&p_ffg, g_ffg16);
    cudaGetSymbolAddress(&p_wqkv, g_w16qkv);
    cudaGetSymbolAddress(&p_wo, g_w16o);
    cudaGetSymbolAddress(&p_wff, g_w16ff);
    cudaGetSymbolAddress(&p_wfo, g_w16fo);
    __half* xmod = (__half*)p_xmod;
    __half* q = (__half*)p_q; __half* k = (__half*)p_k; __half* v = (__half*)p_v;
    __half* attn = (__half*)p_attn; float* h2 = (float*)p_h2; __half* ffg = (__half*)p_ffg;
    __half* wqkv = (__half*)p_wqkv; __half* wo = (__half*)p_wo;
    __half* wff = (__half*)p_wff; __half* wfo = (__half*)p_wfo;

    cudaFuncSetAttribute(attn_h, cudaFuncAttributeMaxDynamicSharedMemorySize, ATT_SMEM_BYTES);
    cudaFuncSetAttribute(gemm_h<0>, cudaFuncAttributeMaxDynamicSharedMemorySize, GEMM_SMEM_BYTES);
    cudaFuncSetAttribute(gemm_h<1>, cudaFuncAttributeMaxDynamicSharedMemorySize, GEMM_SMEM_BYTES);
    cudaFuncSetAttribute(gemm_h<2>, cudaFuncAttributeMaxDynamicSharedMemorySize, GEMM_SMEM_BYTES);
    cudaFuncSetAttribute(gemm_h<3>, cudaFuncAttributeMaxDynamicSharedMemorySize, GEMM_SMEM_BYTES);

    // prep
    k_mods<<<(NBATCH * 6 * HID + 255) / 256, 256>>>(temb, sst);
    k_xmod1<<<(MROWS * HID / 8 + 255) / 256, 256>>>(hidden);
    k_wprep<<<(int)(TOT_CH / 1024), 256>>>(Wq, Wk, Wv, Wo, Wff, Wfo);

    // fused QKV GEMM: [4096, 6144] (bm-fastest raster), fp16 outputs
    gemm_h<1><<<dim3(MROWS / 128, 3 * HID / 128), 256, GEMM_SMEM_BYTES>>>(
        xmod, wqkv, bq, bk, bv, nullptr, HID, nullptr);

    // fused per-head LN on q (scaled) and k
    k_ln16qk<<<(2 * NVEC) / 8, 256>>>(q, k, 0.08838834764831845f);

    attn_h<<<dim3(SLEN / 128, NBATCH * NHEADS), 256, ATT_SMEM_BYTES>>>(q, k, v, attn);

    // O-proj + residual + mlp-modulation (bn-fastest)
    gemm_h<0><<<dim3(HID / 128, MROWS / 128), 256, GEMM_SMEM_BYTES>>>(
        attn, wo, bo, nullptr, nullptr, nullptr, HID, hidden);

    // FF1 + GEGLU (bm-fastest)
    gemm_h<2><<<dim3(MROWS / 128, 2 * FFD / 128), 256, GEMM_SMEM_BYTES>>>(
        xmod, wff, bff, nullptr, nullptr, nullptr, HID, nullptr);

    // FF2 + final residual (bn-fastest)
    gemm_h<3><<<dim3(HID / 128, MROWS / 128), 256, GEMM_SMEM_BYTES>>>(
        ffg, wfo, bfo, nullptr, nullptr, out, FFD, h2);
}